// round 12
// baseline (speedup 1.0000x reference)
#include <cuda_runtime.h>

#define HIDDEN 51
#define JP 64
#define KU 52            // U reg rows: 0..50 = U, 51 = combined bias (h==1)
#define L_SEQ 1000
#define NBLK 128
#define NBG 4            // batches per group
#define THREADS 256      // 2 groups x 128

typedef unsigned long long ull;

// Gate-interleaved weights: g_U4[row*JP + j] = (i,f,g,o); row 51 = combined bias
__device__ float4 g_U4[KU * JP];
__device__ float4 g_W4[JP];   // x weights per j
__device__ float  g_L[JP];    // lin_w per j

// ---------- f32x2 helpers (exact packed fp32) ----------
__device__ __forceinline__ ull pk2(float lo, float hi) {
    ull r; asm("mov.b64 %0, {%1, %2};" : "=l"(r) : "f"(lo), "f"(hi)); return r;
}
__device__ __forceinline__ void up2(float& lo, float& hi, ull v) {
    asm("mov.b64 {%0, %1}, %2;" : "=f"(lo), "=f"(hi) : "l"(v));
}
__device__ __forceinline__ ull f2fma(ull a, ull b, ull c) {
    ull d; asm("fma.rn.f32x2 %0, %1, %2, %3;" : "=l"(d) : "l"(a), "l"(b), "l"(c)); return d;
}
__device__ __forceinline__ ull f2add(ull a, ull b) {
    ull d; asm("add.rn.f32x2 %0, %1, %2;" : "=l"(d) : "l"(a), "l"(b)); return d;
}
__device__ __forceinline__ ull shfl_xor64(ull v, int m) {
    unsigned lo, hi;
    asm("mov.b64 {%0,%1}, %2;" : "=r"(lo), "=r"(hi) : "l"(v));
    lo = __shfl_xor_sync(0xffffffffu, lo, m);
    hi = __shfl_xor_sync(0xffffffffu, hi, m);
    ull r; asm("mov.b64 %0, {%1,%2};" : "=l"(r) : "r"(lo), "r"(hi));
    return r;
}
// accurate fast tanh: 1 - 2/(exp(2x)+1); saturates correctly at +-inf
__device__ __forceinline__ float fast_tanh(float xv) {
    float e;
    asm("ex2.approx.f32 %0, %1;" : "=f"(e) : "f"(xv * 2.8853900817779268f));
    float r;
    asm("rcp.approx.f32 %0, %1;" : "=f"(r) : "f"(e + 1.0f));
    return fmaf(-2.0f, r, 1.0f);
}
__device__ __forceinline__ void group_bar(int barid) {
    asm volatile("bar.sync %0, %1;" :: "r"(barid), "r"(128) : "memory");
}

// ---------- prep ----------
__global__ void prep_kernel(const float* __restrict__ W_w, const float* __restrict__ W_b,
                            const float* __restrict__ U_w, const float* __restrict__ U_b,
                            const float* __restrict__ lin_w) {
    int i = blockIdx.x * 128 + threadIdx.x;   // 0 .. 3327 (52 rows x 64 j)
    if (i >= KU * JP) return;
    int k = i >> 6, j = i & 63;
    float4 u = make_float4(0.f, 0.f, 0.f, 0.f);
    if (j < HIDDEN) {
        if (k < HIDDEN) {
            u.x = U_w[(0 * HIDDEN + j) * HIDDEN + k];
            u.y = U_w[(1 * HIDDEN + j) * HIDDEN + k];
            u.z = U_w[(2 * HIDDEN + j) * HIDDEN + k];
            u.w = U_w[(3 * HIDDEN + j) * HIDDEN + k];
        } else {                              // row 51 = combined bias (h == 1)
            u.x = W_b[0 * HIDDEN + j] + U_b[0 * HIDDEN + j];
            u.y = W_b[1 * HIDDEN + j] + U_b[1 * HIDDEN + j];
            u.z = W_b[2 * HIDDEN + j] + U_b[2 * HIDDEN + j];
            u.w = W_b[3 * HIDDEN + j] + U_b[3 * HIDDEN + j];
        }
    }
    g_U4[i] = u;
    if (i < JP) {
        float4 w = make_float4(0.f, 0.f, 0.f, 0.f);
        float lw = 0.f;
        if (i < HIDDEN) {
            w.x = W_w[0 * HIDDEN + i]; w.y = W_w[1 * HIDDEN + i];
            w.z = W_w[2 * HIDDEN + i]; w.w = W_w[3 * HIDDEN + i];
            lw = lin_w[i];
        }
        g_W4[i] = w; g_L[i] = lw;
    }
}

// ---------- main ----------
// 256 threads = 2 groups x 128; group = 4 batches.
// Thread = (j, gate-pair): j = gtid>>1, gp = gtid&1 (0 -> (i,f), 1 -> (g,o)).
// FULL k per thread (U = 52 pairs = 104 regs) -> accumulators are COMPLETE gates.
// No k-combine; one xor-1 shuffle exchange; ONE barrier per step (double-buffered h).
__global__ void __launch_bounds__(THREADS, 1)
lstm_main(const float* __restrict__ x, const float* __restrict__ lin_b,
          float* __restrict__ out) {
    // h duplicated: row k = [(h,h)b0,(h,h)b1,(h,h)b2,(h,h)b3] = 32B
    __shared__ __align__(16) ull h_shd[2][2][KU][NBG];   // [group][buf][row][batch]
    __shared__ ull redp[2][2][4][2];                     // [group][t&1][warp][gp] f32x2

    const int tid  = threadIdx.x;
    const int g    = tid >> 7;
    const int gtid = tid & 127;
    const int j    = gtid >> 1;       // hidden unit
    const int gp   = gtid & 1;        // 0: (i,f)  1: (g,o)
    const int lane = tid & 31;
    const int w    = gtid >> 5;       // warp within group (0..3)
    const int b0   = blockIdx.x * 8 + g * NBG;

    // Full-k register U for my (j, gate-pair): 52 pairs (104 regs)
    ull u[KU];
#pragma unroll
    for (int k = 0; k < KU; k++) {
        float4 v = g_U4[k * JP + j];
        u[k] = gp ? pk2(v.z, v.w) : pk2(v.x, v.y);
    }
    float4 wv = g_W4[j];
    const ull   wp  = gp ? pk2(wv.z, wv.w) : pk2(wv.x, wv.y);
    const float lw  = g_L[j];
    const float lbv = lin_b[0];

    // init h: zeros; bias row 51 = (1,1) x4 in BOTH buffers (never rewritten)
    for (int i = tid; i < 2 * 2 * KU * NBG; i += THREADS) {
        int row = (i >> 2) % KU;
        ((ull*)h_shd)[i] = (row == HIDDEN) ? pk2(1.f, 1.f) : 0ULL;
    }
    __syncthreads();

    // cell state for my 2 owned batches (b = gp*2 + s); x for all 4 batches
    float c0 = 0.f, c1 = 0.f;
    float xq[NBG];
#pragma unroll
    for (int q = 0; q < NBG; q++) xq[q] = x[(b0 + q) * L_SEQ + 0];

    for (int t = 0; t < L_SEQ; ++t) {
        const int rb = t & 1, wb = rb ^ 1;

        // ---- phase A: full-k complete gates for all 4 batches ----
        ull a0 = f2fma(pk2(xq[0], xq[0]), wp, 0ULL);
        ull a1 = f2fma(pk2(xq[1], xq[1]), wp, 0ULL);
        ull a2 = f2fma(pk2(xq[2], xq[2]), wp, 0ULL);
        ull a3 = f2fma(pk2(xq[3], xq[3]), wp, 0ULL);
        const ull* hr = &h_shd[g][rb][0][0];
#pragma unroll
        for (int k = 0; k < KU; k++) {
            ulonglong2 hA = *(const ulonglong2*)&hr[k * 4 + 0];  // (h,h)b0,(h,h)b1
            ulonglong2 hB = *(const ulonglong2*)&hr[k * 4 + 2];  // (h,h)b2,(h,h)b3
            a0 = f2fma(hA.x, u[k], a0);
            a1 = f2fma(hA.y, u[k], a1);
            a2 = f2fma(hB.x, u[k], a2);
            a3 = f2fma(hB.y, u[k], a3);
        }

        // prefetch next x (hidden under exchange/update)
        float xn[NBG];
        {
            int tn = (t + 1 < L_SEQ) ? t + 1 : t;
#pragma unroll
            for (int q = 0; q < NBG; q++) xn[q] = x[(b0 + q) * L_SEQ + tn];
        }

        // ---- exchange with my gate-partner (lane^1): one xor-1 round ----
        // even keeps batches 0,1 (sends its 2,3); odd keeps 2,3 (sends its 0,1)
        ull e0 = shfl_xor64(gp ? a0 : a2, 1);
        ull e1 = shfl_xor64(gp ? a1 : a3, 1);
        ull s_if0 = gp ? e0 : a0;
        ull s_if1 = gp ? e1 : a1;
        ull s_go0 = gp ? a2 : e0;
        ull s_go1 = gp ? a3 : e1;

        // ---- update c/h for (j, my 2 batches) ----
        float gi, gf, gg, go, h0, h1;
        up2(gi, gf, s_if0); up2(gg, go, s_go0);
        c0 = fmaf(gf, c0, gi * gg);             // faithful: no sigmoids
        h0 = go * fast_tanh(c0);
        up2(gi, gf, s_if1); up2(gg, go, s_go1);
        c1 = fmaf(gf, c1, gi * gg);
        h1 = go * fast_tanh(c1);

        // ---- h store: even writes batches 0,1 halves; odd writes 2,3 ----
        if (j < HIDDEN) {
            ulonglong2 v; v.x = pk2(h0, h0); v.y = pk2(h1, h1);
            *(ulonglong2*)&h_shd[g][wb][j][gp * 2] = v;
        }
#pragma unroll
        for (int q = 0; q < NBG; q++) xq[q] = xn[q];

        group_bar(g + 1);

        // ---- lagged output store for step t-1 (ordered by the bar) ----
        if (t > 0 && gtid < NBG) {
            int b = gtid, pb = (t - 1) & 1;
            float acc = lbv;
#pragma unroll
            for (int ww = 0; ww < 4; ww++) {
                float lo, hi; up2(lo, hi, redp[g][pb][ww][b >> 1]);
                acc += (b & 1) ? hi : lo;
            }
            out[(b0 + b) * L_SEQ + (t - 1)] = acc;
        }

        // ---- output partials AFTER the bar (overlaps next phase A) ----
        ull pp = pk2(h0 * lw, h1 * lw);     // (my batch pair)
        pp = f2add(pp, shfl_xor64(pp, 2));
        pp = f2add(pp, shfl_xor64(pp, 4));
        pp = f2add(pp, shfl_xor64(pp, 8));
        pp = f2add(pp, shfl_xor64(pp, 16));
        if (lane < 2) redp[g][t & 1][w][lane] = pp;   // lane0: (b0,b1), lane1: (b2,b3)
    }

    // ---- tail: flush output for the final step ----
    group_bar(g + 1);
    if (gtid < NBG) {
        int b = gtid, pb = (L_SEQ - 1) & 1;
        float acc = lbv;
#pragma unroll
        for (int ww = 0; ww < 4; ww++) {
            float lo, hi; up2(lo, hi, redp[g][pb][ww][b >> 1]);
            acc += (b & 1) ? hi : lo;
        }
        out[(b0 + b) * L_SEQ + (L_SEQ - 1)] = acc;
    }
}

extern "C" void kernel_launch(void* const* d_in, const int* in_sizes, int n_in,
                              void* d_out, int out_size) {
    (void)in_sizes; (void)n_in; (void)out_size;
    const float* x     = (const float*)d_in[0];
    const float* W_w   = (const float*)d_in[1];
    const float* W_b   = (const float*)d_in[2];
    const float* U_w   = (const float*)d_in[3];
    const float* U_b   = (const float*)d_in[4];
    const float* lin_w = (const float*)d_in[5];
    const float* lin_b = (const float*)d_in[6];
    // d_in[7] = future (static 0) — ignored.

    prep_kernel<<<26, 128>>>(W_w, W_b, U_w, U_b, lin_w);
    lstm_main<<<NBLK, THREADS>>>(x, lin_b, (float*)d_out);
}